// round 4
// baseline (speedup 1.0000x reference)
#include <cuda_runtime.h>
#include <cuda_fp16.h>
#include <cstdint>

// ---------------------------------------------------------------------------
// Problem constants
// ---------------------------------------------------------------------------
static constexpr int IN_F   = 512;
static constexpr int OUT_F  = 512;
static constexpr int NEXP   = 8;
static constexpr int NGRP   = 32;
static constexpr int TPG    = 2048;

// Mixed (per-group) weights in fp16 + bias in fp32, static device scratch.
__device__ __half g_w[(size_t)NGRP * OUT_F * IN_F];   // [g][o][i], 16.8 MB
__device__ float  g_b[NGRP * OUT_F];                  // [g][o]

// ---------------------------------------------------------------------------
// Helpers
// ---------------------------------------------------------------------------
__device__ __forceinline__ uint32_t smem_u32(const void* p) {
    uint32_t a;
    asm("{ .reg .u64 t; cvta.to.shared.u64 t, %1; cvt.u32.u64 %0, t; }"
        : "=r"(a) : "l"(p));
    return a;
}

__device__ __forceinline__ uint32_t sw128(uint32_t o) {
    return o ^ ((o >> 3) & 0x70);
}

__device__ __forceinline__ void ldsm4(uint32_t r[4], uint32_t addr) {
    asm volatile("ldmatrix.sync.aligned.m8n8.x4.shared.b16 {%0,%1,%2,%3}, [%4];"
                 : "=r"(r[0]), "=r"(r[1]), "=r"(r[2]), "=r"(r[3]) : "r"(addr));
}

__device__ __forceinline__ void mma16816(float c[4], const uint32_t a[4],
                                         uint32_t b0, uint32_t b1) {
    asm volatile(
        "mma.sync.aligned.m16n8k16.row.col.f32.f16.f16.f32 "
        "{%0,%1,%2,%3}, {%4,%5,%6,%7}, {%8,%9}, {%0,%1,%2,%3};"
        : "+f"(c[0]), "+f"(c[1]), "+f"(c[2]), "+f"(c[3])
        : "r"(a[0]), "r"(a[1]), "r"(a[2]), "r"(a[3]), "r"(b0), "r"(b1));
}

#define CP_ASYNC16(dst, src) \
    asm volatile("cp.async.cg.shared.global [%0], [%1], 16;" :: "r"(dst), "l"(src))
#define CP_COMMIT()  asm volatile("cp.async.commit_group;" ::: "memory")
#define CP_WAIT0()   asm volatile("cp.async.wait_group 0;" ::: "memory")

// ---------------------------------------------------------------------------
// Kernel 1: mix expert weights -> fp16, per-group
// ---------------------------------------------------------------------------
__global__ void __launch_bounds__(256) mix_w_kernel(const float* __restrict__ coeff,
                                                    const float* __restrict__ we,
                                                    const float* __restrict__ ws) {
    __shared__ float sc[NGRP * NEXP];
    sc[threadIdx.x] = coeff[threadIdx.x];   // 256 == 32*8
    __syncthreads();
    int idx = blockIdx.x * 256 + threadIdx.x;     // 0 .. 512*512-1
    float w[NEXP];
#pragma unroll
    for (int e = 0; e < NEXP; e++) w[e] = we[(size_t)e * OUT_F * IN_F + idx];
    float shared_w = ws[idx];
#pragma unroll 4
    for (int g = 0; g < NGRP; g++) {
        float acc = shared_w;
#pragma unroll
        for (int e = 0; e < NEXP; e++) acc = fmaf(sc[g * NEXP + e], w[e], acc);
        g_w[(size_t)g * OUT_F * IN_F + idx] = __float2half_rn(acc);
    }
}

__global__ void __launch_bounds__(256) mix_b_kernel(const float* __restrict__ coeff,
                                                    const float* __restrict__ be,
                                                    const float* __restrict__ bs) {
    int idx = blockIdx.x * 256 + threadIdx.x;     // 0 .. 32*512-1
    int g = idx >> 9, o = idx & 511;
    float acc = bs[o];
#pragma unroll
    for (int e = 0; e < NEXP; e++) acc = fmaf(coeff[g * NEXP + e], be[e * OUT_F + o], acc);
    g_b[idx] = acc;
}

// ---------------------------------------------------------------------------
// Kernel 2: grouped GEMM  out[g] = x_g @ W_g^T + b_g  via mma.sync (HMMA)
// CTA tile: M=128, N=256, K-chunk=64, double buffered; 512 threads (16 warps),
// warp tile 32x64 (2 m16 x 8 n8).
// ---------------------------------------------------------------------------
static constexpr int KC = 64;
static constexpr int OFF_BIAS = 0;                       // 256 f32 = 1 KB
static constexpr int OFF_A0   = 1024;                    // 128x64 fp16 = 16 KB
static constexpr int OFF_A1   = OFF_A0 + 16384;          // 17408
static constexpr int OFF_B0   = OFF_A1 + 16384;          // 33792 (256x64 fp16 = 32 KB)
static constexpr int OFF_B1   = OFF_B0 + 32768;          // 66560
static constexpr int SMEM_TOTAL = OFF_B1 + 32768;        // 99328

// A: 128 rows x 64 fp32 -> regs (4x float4 per thread; 4 threads/row)
__device__ __forceinline__ void ldgA(const float* __restrict__ xA, int kb, int tid,
                                     float4 v[4]) {
    int row = tid >> 2, q = tid & 3;
    const float4* p = reinterpret_cast<const float4*>(xA + (size_t)row * IN_F + kb + q * 16);
    v[0] = p[0]; v[1] = p[1]; v[2] = p[2]; v[3] = p[3];
}

__device__ __forceinline__ void stsA(char* smem, int aOff, int tid, const float4 v[4]) {
    int row = tid >> 2, q = tid & 3;
    uint4 u0, u1;
    __half2 h;
    h = __floats2half2_rn(v[0].x, v[0].y); u0.x = *reinterpret_cast<uint32_t*>(&h);
    h = __floats2half2_rn(v[0].z, v[0].w); u0.y = *reinterpret_cast<uint32_t*>(&h);
    h = __floats2half2_rn(v[1].x, v[1].y); u0.z = *reinterpret_cast<uint32_t*>(&h);
    h = __floats2half2_rn(v[1].z, v[1].w); u0.w = *reinterpret_cast<uint32_t*>(&h);
    h = __floats2half2_rn(v[2].x, v[2].y); u1.x = *reinterpret_cast<uint32_t*>(&h);
    h = __floats2half2_rn(v[2].z, v[2].w); u1.y = *reinterpret_cast<uint32_t*>(&h);
    h = __floats2half2_rn(v[3].x, v[3].y); u1.z = *reinterpret_cast<uint32_t*>(&h);
    h = __floats2half2_rn(v[3].z, v[3].w); u1.w = *reinterpret_cast<uint32_t*>(&h);
    uint32_t o0 = sw128((uint32_t)(row * 128 + (q * 2) * 16));
    uint32_t o1 = sw128((uint32_t)(row * 128 + (q * 2 + 1) * 16));
    *reinterpret_cast<uint4*>(smem + aOff + o0) = u0;
    *reinterpret_cast<uint4*>(smem + aOff + o1) = u1;
}

// B: 256 rows x 64 fp16 via cp.async (2 threads/row, 4x16B each)
__device__ __forceinline__ void cpB(uint32_t bOffS, const __half* __restrict__ Wg,
                                    int kb, int n_base, int tid) {
    int row = tid >> 1, h = tid & 1;
    const __half* src = Wg + (size_t)(n_base + row) * IN_F + kb + h * 32;
#pragma unroll
    for (int j = 0; j < 4; j++) {
        uint32_t dst = bOffS + sw128((uint32_t)(row * 128 + (h * 4 + j) * 16));
        CP_ASYNC16(dst, src + j * 8);
    }
}

__device__ __forceinline__ void compute_chunk(uint32_t aBase, uint32_t bBase,
                                              int wm, int wn, int lane,
                                              float acc[2][8][4]) {
#pragma unroll
    for (int kk = 0; kk < 4; kk++) {
        int c0 = kk * 2;
        uint32_t a[2][4];
#pragma unroll
        for (int mt = 0; mt < 2; mt++) {
            int r = wm * 32 + mt * 16 + (lane & 15);
            int c = c0 + (lane >> 4);
            ldsm4(a[mt], aBase + sw128((uint32_t)(r * 128 + c * 16)));
        }
        uint32_t bb[4][4];
#pragma unroll
        for (int nt = 0; nt < 4; nt++) {
            int r = wn * 64 + nt * 16 + (lane & 7) + ((lane & 16) ? 8 : 0);
            int c = c0 + ((lane >> 3) & 1);
            ldsm4(bb[nt], bBase + sw128((uint32_t)(r * 128 + c * 16)));
        }
#pragma unroll
        for (int mt = 0; mt < 2; mt++)
#pragma unroll
            for (int nt = 0; nt < 4; nt++) {
                mma16816(acc[mt][nt * 2 + 0], a[mt], bb[nt][0], bb[nt][1]);
                mma16816(acc[mt][nt * 2 + 1], a[mt], bb[nt][2], bb[nt][3]);
            }
    }
}

__global__ void __launch_bounds__(512, 1) mole_gemm(const float* __restrict__ x,
                                                    float* __restrict__ out) {
    extern __shared__ char smem[];
    uint32_t sb = smem_u32(smem);
    int tid = threadIdx.x, wid = tid >> 5, lane = tid & 31;
    int wm = wid & 3, wn = wid >> 2;          // warp grid 4(m) x 4(n)

    int b = blockIdx.x;
    int ntile = b & 1;            // 2 n-tiles of 256
    int mtile = (b >> 1) & 15;    // 16 m-tiles of 128
    int g     = b >> 5;           // 32 groups
    int m_base = g * TPG + mtile * 128;
    int n_base = ntile * 256;
    const float*  xA = x + (size_t)m_base * IN_F;
    const __half* Wg = g_w + (size_t)g * OUT_F * IN_F;

    float* sbias = reinterpret_cast<float*>(smem + OFF_BIAS);
    if (tid < 256) sbias[tid] = g_b[g * OUT_F + n_base + tid];

    float acc[2][8][4];
#pragma unroll
    for (int i = 0; i < 2; i++)
#pragma unroll
        for (int j = 0; j < 8; j++)
#pragma unroll
            for (int l = 0; l < 4; l++) acc[i][j][l] = 0.0f;

    // prologue: chunk 0 -> buffer 0
    float4 av[4];
    ldgA(xA, 0, tid, av);
    cpB(sb + OFF_B0, Wg, 0, n_base, tid);
    CP_COMMIT();
    stsA(smem, OFF_A0, tid, av);
    CP_WAIT0();
    __syncthreads();

#pragma unroll 1
    for (int k = 0; k < 8; k++) {
        int cur = k & 1;
        if (k < 7) {
            cpB(sb + (cur ? OFF_B0 : OFF_B1), Wg, (k + 1) * KC, n_base, tid);
            CP_COMMIT();
            ldgA(xA, (k + 1) * KC, tid, av);
        }
        compute_chunk(sb + (cur ? OFF_A1 : OFF_A0),
                      sb + (cur ? OFF_B1 : OFF_B0), wm, wn, lane, acc);
        if (k < 7) {
            stsA(smem, cur ? OFF_A0 : OFF_A1, tid, av);
            CP_WAIT0();
        }
        __syncthreads();
    }

    // epilogue: direct fragment stores + bias
#pragma unroll
    for (int mt = 0; mt < 2; mt++) {
        int r0 = m_base + wm * 32 + mt * 16 + (lane >> 2);
#pragma unroll
        for (int nt8 = 0; nt8 < 8; nt8++) {
            int cl = wn * 64 + nt8 * 8 + (lane & 3) * 2;
            float bx = sbias[cl], by = sbias[cl + 1];
            float2 v0 = make_float2(acc[mt][nt8][0] + bx, acc[mt][nt8][1] + by);
            float2 v1 = make_float2(acc[mt][nt8][2] + bx, acc[mt][nt8][3] + by);
            *reinterpret_cast<float2*>(out + (size_t)r0 * OUT_F + n_base + cl) = v0;
            *reinterpret_cast<float2*>(out + (size_t)(r0 + 8) * OUT_F + n_base + cl) = v1;
        }
    }
}

// ---------------------------------------------------------------------------
// launch
// ---------------------------------------------------------------------------
extern "C" void kernel_launch(void* const* d_in, const int* in_sizes, int n_in,
                              void* d_out, int out_size) {
    const float* x  = (const float*)d_in[0];
    const float* co = (const float*)d_in[1];
    const float* we = (const float*)d_in[2];
    const float* be = (const float*)d_in[3];
    const float* ws = (const float*)d_in[4];
    const float* bs = (const float*)d_in[5];
    float* out = (float*)d_out;

    cudaFuncSetAttribute(mole_gemm, cudaFuncAttributeMaxDynamicSharedMemorySize,
                         SMEM_TOTAL);

    mix_w_kernel<<<(OUT_F * IN_F) / 256, 256>>>(co, we, ws);
    mix_b_kernel<<<(NGRP * OUT_F) / 256, 256>>>(co, be, bs);
    mole_gemm<<<NGRP * 16 * 2, 512, SMEM_TOTAL>>>(x, out);
}

// round 5
// speedup vs baseline: 1.1116x; 1.1116x over previous
#include <cuda_runtime.h>
#include <cuda_fp16.h>
#include <cstdint>

// ---------------------------------------------------------------------------
// Problem constants
// ---------------------------------------------------------------------------
static constexpr int IN_F   = 512;
static constexpr int OUT_F  = 512;
static constexpr int NEXP   = 8;
static constexpr int NGRP   = 32;
static constexpr int TPG    = 2048;

// Mixed (per-group) weights in fp16 + bias in fp32, static device scratch.
__device__ __half g_w[(size_t)NGRP * OUT_F * IN_F];   // [g][o][i], 16.8 MB
__device__ float  g_b[NGRP * OUT_F];                  // [g][o]

// ---------------------------------------------------------------------------
// Helpers
// ---------------------------------------------------------------------------
__device__ __forceinline__ uint32_t smem_u32(const void* p) {
    uint32_t a;
    asm("{ .reg .u64 t; cvta.to.shared.u64 t, %1; cvt.u32.u64 %0, t; }"
        : "=r"(a) : "l"(p));
    return a;
}

__device__ __forceinline__ uint32_t sw128(uint32_t o) {
    return o ^ ((o >> 3) & 0x70);
}

__device__ __forceinline__ void ldsm4(uint32_t r[4], uint32_t addr) {
    asm volatile("ldmatrix.sync.aligned.m8n8.x4.shared.b16 {%0,%1,%2,%3}, [%4];"
                 : "=r"(r[0]), "=r"(r[1]), "=r"(r[2]), "=r"(r[3]) : "r"(addr));
}

__device__ __forceinline__ float2 lds64(uint32_t addr) {
    float2 v;
    asm volatile("ld.shared.v2.f32 {%0,%1}, [%2];"
                 : "=f"(v.x), "=f"(v.y) : "r"(addr));
    return v;
}

__device__ __forceinline__ uint32_t packh2(float2 p) {
    __half2 h = __floats2half2_rn(p.x, p.y);
    return *reinterpret_cast<uint32_t*>(&h);
}

__device__ __forceinline__ void mma16816(float c[4], const uint32_t a[4],
                                         uint32_t b0, uint32_t b1) {
    asm volatile(
        "mma.sync.aligned.m16n8k16.row.col.f32.f16.f16.f32 "
        "{%0,%1,%2,%3}, {%4,%5,%6,%7}, {%8,%9}, {%0,%1,%2,%3};"
        : "+f"(c[0]), "+f"(c[1]), "+f"(c[2]), "+f"(c[3])
        : "r"(a[0]), "r"(a[1]), "r"(a[2]), "r"(a[3]), "r"(b0), "r"(b1));
}

#define CP_ASYNC16(dst, src) \
    asm volatile("cp.async.cg.shared.global [%0], [%1], 16;" :: "r"(dst), "l"(src))
#define CP_COMMIT()  asm volatile("cp.async.commit_group;" ::: "memory")
#define CP_WAIT0()   asm volatile("cp.async.wait_group 0;" ::: "memory")
#define CP_WAIT1()   asm volatile("cp.async.wait_group 1;" ::: "memory")

// ---------------------------------------------------------------------------
// Kernel 1: mix expert weights -> fp16, per-group
// ---------------------------------------------------------------------------
__global__ void __launch_bounds__(256) mix_w_kernel(const float* __restrict__ coeff,
                                                    const float* __restrict__ we,
                                                    const float* __restrict__ ws) {
    __shared__ float sc[NGRP * NEXP];
    sc[threadIdx.x] = coeff[threadIdx.x];   // 256 == 32*8
    __syncthreads();
    int idx = blockIdx.x * 256 + threadIdx.x;     // 0 .. 512*512-1
    float w[NEXP];
#pragma unroll
    for (int e = 0; e < NEXP; e++) w[e] = we[(size_t)e * OUT_F * IN_F + idx];
    float shared_w = ws[idx];
#pragma unroll 4
    for (int g = 0; g < NGRP; g++) {
        float acc = shared_w;
#pragma unroll
        for (int e = 0; e < NEXP; e++) acc = fmaf(sc[g * NEXP + e], w[e], acc);
        g_w[(size_t)g * OUT_F * IN_F + idx] = __float2half_rn(acc);
    }
}

__global__ void __launch_bounds__(256) mix_b_kernel(const float* __restrict__ coeff,
                                                    const float* __restrict__ be,
                                                    const float* __restrict__ bs) {
    int idx = blockIdx.x * 256 + threadIdx.x;     // 0 .. 32*512-1
    int g = idx >> 9, o = idx & 511;
    float acc = bs[o];
#pragma unroll
    for (int e = 0; e < NEXP; e++) acc = fmaf(coeff[g * NEXP + e], be[e * OUT_F + o], acc);
    g_b[idx] = acc;
}

// ---------------------------------------------------------------------------
// Kernel 2: grouped GEMM  out[g] = x_g @ W_g^T + b_g  via mma.sync (HMMA)
// CTA tile M=128, N=256, K-chunk=64. 512 threads (16 warps), warp tile 32x64.
// 3-stage cp.async pipeline. A kept fp32 in smem (no register staging);
// A fragments via LDS.64 + F2FP pack, B fragments via ldmatrix.
// ---------------------------------------------------------------------------
static constexpr int KC = 64;
static constexpr int OFF_BIAS   = 0;                     // 256 f32 = 1 KB
static constexpr int STAGE_SZ   = 65536;                 // A 32KB (fp32) + B 32KB (fp16)
static constexpr int OFF_STAGE  = 1024;
static constexpr int SMEM_TOTAL = OFF_STAGE + 3 * STAGE_SZ;   // 197632

__device__ __forceinline__ uint32_t stageA(uint32_t sb, int s) {
    return sb + OFF_STAGE + s * STAGE_SZ;
}
__device__ __forceinline__ uint32_t stageB(uint32_t sb, int s) {
    return sb + OFF_STAGE + s * STAGE_SZ + 32768;
}

// A: 128 rows x 64 fp32, row = 256B, per-row XOR swizzle (cb ^ ((row&7)<<5))
__device__ __forceinline__ void cpA(uint32_t aOffS, const float* __restrict__ xA,
                                    int kb, int tid) {
#pragma unroll
    for (int it = 0; it < 4; it++) {
        int u = tid + it * 512;             // 0..2047 16B-chunks
        int row = u >> 4, c16 = u & 15;
        uint32_t cb = (uint32_t)(c16 * 16);
        uint32_t dst = aOffS + (uint32_t)(row * 256) + (cb ^ ((uint32_t)(row & 7) << 5));
        const float* src = xA + (size_t)row * IN_F + kb + c16 * 4;
        CP_ASYNC16(dst, src);
    }
}

// B: 256 rows x 64 fp16, 128B rows, SW128 swizzle (2 threads/row, 4x16B each)
__device__ __forceinline__ void cpB(uint32_t bOffS, const __half* __restrict__ Wg,
                                    int kb, int n_base, int tid) {
    int row = tid >> 1, h = tid & 1;
    const __half* src = Wg + (size_t)(n_base + row) * IN_F + kb + h * 32;
#pragma unroll
    for (int j = 0; j < 4; j++) {
        uint32_t dst = bOffS + sw128((uint32_t)(row * 128 + (h * 4 + j) * 16));
        CP_ASYNC16(dst, src + j * 8);
    }
}

__device__ __forceinline__ void compute_chunk(uint32_t aBase, uint32_t bBase,
                                              int wm, int wn, int lane,
                                              float acc[2][8][4]) {
    const uint32_t sA   = (uint32_t)((lane >> 2) & 7) << 5;   // row-swizzle const
    const uint32_t colb = (uint32_t)(lane & 3) * 8;           // col-pair byte offset
    const uint32_t rbase0 = aBase + (uint32_t)((wm * 32 + (lane >> 2)) * 256);
#pragma unroll
    for (int kk = 0; kk < 4; kk++) {
        uint32_t cb0 = (uint32_t)(kk * 64) + colb;
        uint32_t a[2][4];
#pragma unroll
        for (int mt = 0; mt < 2; mt++) {
            uint32_t rb = rbase0 + (uint32_t)(mt * 16 * 256);
            // m16n8k16 A fragment: (r, k0), (r+8, k0), (r, k0+8), (r+8, k0+8)
            a[mt][0] = packh2(lds64(rb +            (cb0 ^ sA)));
            a[mt][1] = packh2(lds64(rb + 8 * 256 +  (cb0 ^ sA)));
            a[mt][2] = packh2(lds64(rb +            ((cb0 + 32) ^ sA)));
            a[mt][3] = packh2(lds64(rb + 8 * 256 +  ((cb0 + 32) ^ sA)));
        }
        int c0 = kk * 2;
        uint32_t bb[4][4];
#pragma unroll
        for (int nt = 0; nt < 4; nt++) {
            int r = wn * 64 + nt * 16 + (lane & 7) + ((lane & 16) ? 8 : 0);
            int c = c0 + ((lane >> 3) & 1);
            ldsm4(bb[nt], bBase + sw128((uint32_t)(r * 128 + c * 16)));
        }
#pragma unroll
        for (int mt = 0; mt < 2; mt++)
#pragma unroll
            for (int nt = 0; nt < 4; nt++) {
                mma16816(acc[mt][nt * 2 + 0], a[mt], bb[nt][0], bb[nt][1]);
                mma16816(acc[mt][nt * 2 + 1], a[mt], bb[nt][2], bb[nt][3]);
            }
    }
}

__global__ void __launch_bounds__(512, 1) mole_gemm(const float* __restrict__ x,
                                                    float* __restrict__ out) {
    extern __shared__ char smem[];
    uint32_t sb = smem_u32(smem);
    int tid = threadIdx.x, wid = tid >> 5, lane = tid & 31;
    int wm = wid & 3, wn = wid >> 2;          // warp grid 4(m) x 4(n)

    int b = blockIdx.x;
    int ntile = b & 1;            // 2 n-tiles of 256
    int mtile = (b >> 1) & 15;    // 16 m-tiles of 128
    int g     = b >> 5;           // 32 groups
    int m_base = g * TPG + mtile * 128;
    int n_base = ntile * 256;
    const float*  xA = x + (size_t)m_base * IN_F;
    const __half* Wg = g_w + (size_t)g * OUT_F * IN_F;

    float* sbias = reinterpret_cast<float*>(smem + OFF_BIAS);
    if (tid < 256) sbias[tid] = g_b[g * OUT_F + n_base + tid];

    float acc[2][8][4];
#pragma unroll
    for (int i = 0; i < 2; i++)
#pragma unroll
        for (int j = 0; j < 8; j++)
#pragma unroll
            for (int l = 0; l < 4; l++) acc[i][j][l] = 0.0f;

    // prologue: stages 0 and 1 in flight
    cpA(stageA(sb, 0), xA, 0, tid);
    cpB(stageB(sb, 0), Wg, 0, n_base, tid);
    CP_COMMIT();
    cpA(stageA(sb, 1), xA, KC, tid);
    cpB(stageB(sb, 1), Wg, KC, n_base, tid);
    CP_COMMIT();

#pragma unroll 1
    for (int k = 0; k < 8; k++) {
        if (k == 7) CP_WAIT0(); else CP_WAIT1();
        __syncthreads();
        if (k + 2 < 8) {
            int s = (k + 2) % 3;
            cpA(stageA(sb, s), xA, (k + 2) * KC, tid);
            cpB(stageB(sb, s), Wg, (k + 2) * KC, n_base, tid);
            CP_COMMIT();
        }
        int cs = k % 3;
        compute_chunk(stageA(sb, cs), stageB(sb, cs), wm, wn, lane, acc);
    }

    // epilogue: direct fragment stores + bias
#pragma unroll
    for (int mt = 0; mt < 2; mt++) {
        int r0 = m_base + wm * 32 + mt * 16 + (lane >> 2);
#pragma unroll
        for (int nt8 = 0; nt8 < 8; nt8++) {
            int cl = wn * 64 + nt8 * 8 + (lane & 3) * 2;
            float bx = sbias[cl], by = sbias[cl + 1];
            float2 v0 = make_float2(acc[mt][nt8][0] + bx, acc[mt][nt8][1] + by);
            float2 v1 = make_float2(acc[mt][nt8][2] + bx, acc[mt][nt8][3] + by);
            *reinterpret_cast<float2*>(out + (size_t)r0 * OUT_F + n_base + cl) = v0;
            *reinterpret_cast<float2*>(out + (size_t)(r0 + 8) * OUT_F + n_base + cl) = v1;
        }
    }
}

// ---------------------------------------------------------------------------
// launch
// ---------------------------------------------------------------------------
extern "C" void kernel_launch(void* const* d_in, const int* in_sizes, int n_in,
                              void* d_out, int out_size) {
    const float* x  = (const float*)d_in[0];
    const float* co = (const float*)d_in[1];
    const float* we = (const float*)d_in[2];
    const float* be = (const float*)d_in[3];
    const float* ws = (const float*)d_in[4];
    const float* bs = (const float*)d_in[5];
    float* out = (float*)d_out;

    cudaFuncSetAttribute(mole_gemm, cudaFuncAttributeMaxDynamicSharedMemorySize,
                         SMEM_TOTAL);

    mix_w_kernel<<<(OUT_F * IN_F) / 256, 256>>>(co, we, ws);
    mix_b_kernel<<<(NGRP * OUT_F) / 256, 256>>>(co, be, bs);
    mole_gemm<<<NGRP * 16 * 2, 512, SMEM_TOTAL>>>(x, out);
}